// round 1
// baseline (speedup 1.0000x reference)
#include <cuda_runtime.h>
#include <cuda_bf16.h>

#define NBINS 100
#define EPSF 1e-10f
#define COLS 32

// Global scratch (device globals: no allocation allowed)
__device__ float g_hist[NBINS];
__device__ float g_wss[NBINS];

__global__ void zero_k() {
    int i = threadIdx.x;
    if (i < NBINS) { g_hist[i] = 0.0f; g_wss[i] = 0.0f; }
}

// One warp per block. Each lane owns a private column in the shared
// (hist, wss) table -> no atomics, no bank conflicts in the hot loop.
__global__ __launch_bounds__(32, 8) void hist_k(
    const float4* __restrict__ obs4,
    const float4* __restrict__ wts4,
    const float*  __restrict__ obs_s,
    const float*  __restrict__ wts_s,
    const float*  __restrict__ bins,
    int nvec, int n)
{
    __shared__ float2 sh[NBINS * COLS];   // .x = hist, .y = wss
    const int lane = threadIdx.x;

    #pragma unroll
    for (int i = lane; i < NBINS * COLS; i += 32)
        sh[i] = make_float2(0.0f, 0.0f);
    __syncwarp();

    const float b0   = __ldg(&bins[0]);
    const float bN   = __ldg(&bins[NBINS]);
    const float delta = (bN - b0) * (1.0f / (float)NBINS);
    const float invd  = (float)NBINS / (bN - b0);

    const int stride = gridDim.x * 32;

    for (int v = blockIdx.x * 32 + lane; v < nvec; v += stride) {
        float4 o = obs4[v];
        float4 w = wts4[v];
        #pragma unroll
        for (int e = 0; e < 4; e++) {
            float of = (e == 0) ? o.x : (e == 1) ? o.y : (e == 2) ? o.z : o.w;
            float wf = (e == 0) ? w.x : (e == 1) ? w.y : (e == 2) ? w.z : w.w;
            float t = (of - b0) * invd;
            int j = (int)t;
            j = max(0, min(j, NBINS - 1));
            int jc = min(j, NBINS - 2);
            float left = fmaf((float)jc, delta, b0);
            float frac = (of - left) * invd;
            // ws -> hist[jc+1] (valid j in [0, NBINS-3]); wp -> hist[jc] (valid j in [1, NBINS-2])
            float ws = (j <= NBINS - 3) ? frac * wf : 0.0f;
            float wp = (j >= 1 && j <= NBINS - 2) ? (1.0f - frac) * wf : 0.0f;

            float2 c0 = sh[jc * COLS + lane];
            c0.x += wp; c0.y = fmaf(wp, wp, c0.y);
            sh[jc * COLS + lane] = c0;

            float2 c1 = sh[(jc + 1) * COLS + lane];
            c1.x += ws; c1.y = fmaf(ws, ws, c1.y);
            sh[(jc + 1) * COLS + lane] = c1;
        }
    }

    // Scalar tail (N not divisible by 4), handled by block 0 only.
    if (blockIdx.x == 0) {
        for (int i = nvec * 4 + lane; i < n; i += 32) {
            float of = obs_s[i];
            float wf = wts_s[i];
            float t = (of - b0) * invd;
            int j = (int)t;
            j = max(0, min(j, NBINS - 1));
            int jc = min(j, NBINS - 2);
            float left = fmaf((float)jc, delta, b0);
            float frac = (of - left) * invd;
            float ws = (j <= NBINS - 3) ? frac * wf : 0.0f;
            float wp = (j >= 1 && j <= NBINS - 2) ? (1.0f - frac) * wf : 0.0f;
            float2 c0 = sh[jc * COLS + lane];
            c0.x += wp; c0.y = fmaf(wp, wp, c0.y);
            sh[jc * COLS + lane] = c0;
            float2 c1 = sh[(jc + 1) * COLS + lane];
            c1.x += ws; c1.y = fmaf(ws, ws, c1.y);
            sh[(jc + 1) * COLS + lane] = c1;
        }
    }
    __syncwarp();

    // Reduce this warp's 32 columns per bin, then one global atomic per bin.
    for (int b = lane; b < NBINS; b += 32) {
        float h = 0.0f, s = 0.0f;
        #pragma unroll
        for (int c = 0; c < COLS; c++) {
            float2 vv = sh[b * COLS + c];
            h += vv.x; s += vv.y;
        }
        atomicAdd(&g_hist[b], h);
        atomicAdd(&g_wss[b], s);
    }
}

__device__ __forceinline__ float block_reduce_128(float v, float* shred) {
    // 128 threads
    #pragma unroll
    for (int o = 16; o > 0; o >>= 1) v += __shfl_down_sync(0xFFFFFFFFu, v, o);
    int wid = threadIdx.x >> 5;
    int lid = threadIdx.x & 31;
    if (lid == 0) shred[wid] = v;
    __syncthreads();
    if (wid == 0) {
        v = (lid < 4) ? shred[lid] : 0.0f;
        #pragma unroll
        for (int o = 2; o > 0; o >>= 1) v += __shfl_down_sync(0xFFFFFFFFu, v, o);
        if (lid == 0) shred[0] = v;
    }
    __syncthreads();
    float r = shred[0];
    __syncthreads();
    return r;
}

__global__ void final_k(const float* __restrict__ histo_exp, float* __restrict__ out) {
    __shared__ float shred[4];
    int t = threadIdx.x;  // 128 threads
    float hs = (t < NBINS) ? g_hist[t] : 0.0f;
    float he = (t < NBINS) ? __ldg(&histo_exp[t]) : 0.0f;

    float sum_sim = block_reduce_128(hs, shred);
    float sum_exp = block_reduce_128(he, shred);

    float term = 0.0f;
    if (t < NBINS) {
        float wss = g_wss[t];
        float inv_ss2 = 1.0f / ((sum_sim + EPSF) * (sum_sim + EPSF));
        float inv_se2 = 1.0f / ((sum_exp + EPSF) * (sum_exp + EPSF));
        float unc_sim = wss * inv_ss2 + EPSF;
        float unc_exp = he * (1.0f - he / sum_exp) * inv_se2 + EPSF;
        float d = hs / sum_sim - he / sum_exp;
        term = d * d / (unc_sim + unc_exp);
    }
    float chi2 = block_reduce_128(term, shred);
    if (t == 0) out[0] = chi2;
}

extern "C" void kernel_launch(void* const* d_in, const int* in_sizes, int n_in,
                              void* d_out, int out_size) {
    const float* sim  = (const float*)d_in[0];
    // d_in[1] = exp_observable: unused in the fixed_binning branch
    const float* wts  = (const float*)d_in[2];
    const float* bins = (const float*)d_in[3];
    const float* he   = (const float*)d_in[4];
    int n = in_sizes[0];
    int nvec = n / 4;

    zero_k<<<1, 128>>>();
    hist_k<<<152 * 8, 32>>>((const float4*)sim, (const float4*)wts,
                            sim, wts, bins, nvec, n);
    final_k<<<1, 128>>>(he, (float*)d_out);
}

// round 3
// speedup vs baseline: 1.1457x; 1.1457x over previous
#include <cuda_runtime.h>
#include <cuda_bf16.h>

#define NBINS 100
#define EPSF  1e-10f
#define COLS  32
#define GRID_BLOCKS 1216   // 152 SMs * 8 blocks

// Device-global scratch (device globals are zero-initialized at load;
// the last block resets them each call to keep the invariant).
__device__ float        g_hist[NBINS];
__device__ float        g_wss[NBINS];
__device__ unsigned int g_count;

__device__ __forceinline__ void accum_elem(float2* __restrict__ shl,
                                           float of, float wf,
                                           float b0, float invd)
{
    float t   = (of - b0) * invd;
    float jf  = floorf(t);
    float jcf = fminf(fmaxf(jf, 0.0f), (float)(NBINS - 2));
    int   jc  = (int)jcf;
    float frac = t - jcf;                       // == (of - left)/delta for in-range j
    bool  sub  = (jf >= 0.0f) & (jf <= (float)(NBINS - 3));  // -> bin jc+1
    bool  plus = (jf >= 1.0f) & (jf <= (float)(NBINS - 2));  // -> bin jc
    float ws = sub  ? frac * wf          : 0.0f;
    float wp = plus ? (1.0f - frac) * wf : 0.0f;

    float2 c0 = shl[jc * COLS];
    c0.x += wp; c0.y = fmaf(wp, wp, c0.y);
    shl[jc * COLS] = c0;

    float2 c1 = shl[(jc + 1) * COLS];
    c1.x += ws; c1.y = fmaf(ws, ws, c1.y);
    shl[(jc + 1) * COLS] = c1;
}

__device__ __forceinline__ void accum4(float2* __restrict__ shl,
                                       float4 o, float4 w,
                                       float b0, float invd)
{
    accum_elem(shl, o.x, w.x, b0, invd);
    accum_elem(shl, o.y, w.y, b0, invd);
    accum_elem(shl, o.z, w.z, b0, invd);
    accum_elem(shl, o.w, w.w, b0, invd);
}

__global__ __launch_bounds__(32, 8) void fused_k(
    const float4* __restrict__ obs4,
    const float4* __restrict__ wts4,
    const float*  __restrict__ obs_s,
    const float*  __restrict__ wts_s,
    const float*  __restrict__ bins,
    const float*  __restrict__ histo_exp,
    float*        __restrict__ out,
    int nvec, int n)
{
    __shared__ float2 sh[NBINS * COLS];    // .x = hist, .y = wss ; lane-private columns
    const int lane = threadIdx.x;

    #pragma unroll
    for (int i = lane; i < NBINS * COLS; i += 32)
        sh[i] = make_float2(0.0f, 0.0f);
    __syncwarp();

    const float b0   = __ldg(&bins[0]);
    const float bN   = __ldg(&bins[NBINS]);
    const float invd = (float)NBINS / (bN - b0);

    float2* shl = &sh[lane];
    const int stride = GRID_BLOCKS * 32;

    int v = blockIdx.x * 32 + lane;
    for (; v < nvec - stride; v += 2 * stride) {
        float4 oa = obs4[v];
        float4 wa = wts4[v];
        float4 ob = obs4[v + stride];
        float4 wb = wts4[v + stride];
        accum4(shl, oa, wa, b0, invd);
        accum4(shl, ob, wb, b0, invd);
    }
    if (v < nvec) {
        float4 o = obs4[v];
        float4 w = wts4[v];
        accum4(shl, o, w, b0, invd);
    }

    // Scalar tail (N % 4), block 0 only (empty for N = 2^25).
    if (blockIdx.x == 0) {
        for (int i = nvec * 4 + lane; i < n; i += 32)
            accum_elem(shl, obs_s[i], wts_s[i], b0, invd);
    }
    __syncwarp();

    // Conflict-free rotated per-bin reduction: lane owns bins g*32+lane,
    // reads column (lane + t) & 31 -> per-phase bank permutation, 0 conflicts.
    #pragma unroll
    for (int g = 0; g < 4; g++) {
        int b = g * 32 + lane;
        if (b < NBINS) {
            float h = 0.0f, s = 0.0f;
            #pragma unroll
            for (int t = 0; t < 32; t++) {
                int c = (lane + t) & 31;
                float2 vv = sh[b * COLS + c];
                h += vv.x; s += vv.y;
            }
            atomicAdd(&g_hist[b], h);
            atomicAdd(&g_wss[b], s);
        }
    }

    // Last-block-done: final chi^2 + reset for next graph replay.
    __syncwarp();
    __threadfence();
    unsigned int done = 0;
    if (lane == 0) done = atomicAdd(&g_count, 1u);
    done = __shfl_sync(0xFFFFFFFFu, done, 0);
    if (done == (unsigned)(GRID_BLOCKS - 1)) {
        __threadfence();
        float hs[4], ss[4], he[4];
        float hsum = 0.0f, esum = 0.0f;
        #pragma unroll
        for (int g = 0; g < 4; g++) {
            int b = g * 32 + lane;
            bool ok = (b < NBINS);
            hs[g] = ok ? __ldcg(&g_hist[b]) : 0.0f;
            ss[g] = ok ? __ldcg(&g_wss[b])  : 0.0f;
            he[g] = ok ? __ldg(&histo_exp[b]) : 0.0f;
            hsum += hs[g];
            esum += he[g];
        }
        #pragma unroll
        for (int o = 16; o > 0; o >>= 1) {
            hsum += __shfl_xor_sync(0xFFFFFFFFu, hsum, o);
            esum += __shfl_xor_sync(0xFFFFFFFFu, esum, o);
        }
        const float inv_ss2 = 1.0f / ((hsum + EPSF) * (hsum + EPSF));
        const float inv_se2 = 1.0f / ((esum + EPSF) * (esum + EPSF));
        const float inv_ss  = 1.0f / hsum;
        const float inv_se  = 1.0f / esum;
        float chi = 0.0f;
        #pragma unroll
        for (int g = 0; g < 4; g++) {
            int b = g * 32 + lane;
            if (b < NBINS) {
                float unc_sim = ss[g] * inv_ss2 + EPSF;
                float unc_exp = he[g] * (1.0f - he[g] * inv_se) * inv_se2 + EPSF;
                float d = hs[g] * inv_ss - he[g] * inv_se;
                chi += d * d / (unc_sim + unc_exp);
            }
        }
        #pragma unroll
        for (int o = 16; o > 0; o >>= 1)
            chi += __shfl_xor_sync(0xFFFFFFFFu, chi, o);
        if (lane == 0) out[0] = chi;

        // Reset globals for the next replay (all other blocks already done).
        #pragma unroll
        for (int g = 0; g < 4; g++) {
            int b = g * 32 + lane;
            if (b < NBINS) {
                __stcg(&g_hist[b], 0.0f);
                __stcg(&g_wss[b], 0.0f);
            }
        }
        __threadfence();
        if (lane == 0) atomicExch(&g_count, 0u);
    }
}

extern "C" void kernel_launch(void* const* d_in, const int* in_sizes, int n_in,
                              void* d_out, int out_size) {
    const float* sim  = (const float*)d_in[0];
    // d_in[1] = exp_observable: unused in the fixed_binning branch
    const float* wts  = (const float*)d_in[2];
    const float* bins = (const float*)d_in[3];
    const float* he   = (const float*)d_in[4];
    int n    = in_sizes[0];
    int nvec = n / 4;

    // Hint the driver to configure max shared-memory carveout (occupancy).
    cudaFuncSetAttribute(fused_k, cudaFuncAttributePreferredSharedMemoryCarveout, 100);

    fused_k<<<GRID_BLOCKS, 32>>>((const float4*)sim, (const float4*)wts,
                                 sim, wts, bins, he, (float*)d_out, nvec, n);
}

// round 4
// speedup vs baseline: 1.7430x; 1.5214x over previous
#include <cuda_runtime.h>
#include <cuda_bf16.h>

#define NBINS 100
#define EPSF  1e-10f
#define COLS  32
#define GRID_BLOCKS 1216   // 152 SMs * 8 blocks

__device__ float        g_hist[NBINS];
__device__ float        g_wss[NBINS];
__device__ unsigned int g_count;

struct Contrib {
    int   jc;
    float wp, wpq, ws, wsq;
};

// Per-element bin/weight computation: independent across elements (hoistable).
__device__ __forceinline__ Contrib elem_contrib(float of, float wf,
                                                float invd, float nb0)
{
    Contrib c;
    float t  = fmaf(of, invd, nb0);          // (of - b0) * invd
    float jf = floorf(t);
    float fr = t - jf;                        // fractional part
    int   j  = (int)jf;                       // exact: jf is integral
    c.jc     = min(max(j, 0), NBINS - 2);
    bool sub  = ((unsigned)j       <= (unsigned)(NBINS - 3)); // j in [0,97] -> bin jc+1
    bool plus = ((unsigned)(j - 1) <= (unsigned)(NBINS - 3)); // j in [1,98] -> bin jc
    c.ws  = sub  ? fr * wf           : 0.0f;
    c.wp  = plus ? (1.0f - fr) * wf  : 0.0f;
    c.wsq = c.ws * c.ws;
    c.wpq = c.wp * c.wp;
    return c;
}

// Two elements' RMWs with collision merge so all 4 LDS issue before any STS.
__device__ __forceinline__ void pair_rmw(float2* __restrict__ shl,
                                         Contrib a, Contrib b)
{
    int d = b.jc - a.jc;
    bool m0 = (d == 0), mp = (d == 1), mm = (d == -1);
    // element-b absorbs colliding element-a contributions
    float addp  = m0 ? a.wp  : (mp ? a.ws  : 0.0f);
    float addpq = m0 ? a.wpq : (mp ? a.wsq : 0.0f);
    float adds  = m0 ? a.ws  : (mm ? a.wp  : 0.0f);
    float addsq = m0 ? a.wsq : (mm ? a.wpq : 0.0f);
    b.wp  += addp;  b.wpq += addpq;
    b.ws  += adds;  b.wsq += addsq;
    // zero absorbed element-a contributions
    bool za = m0 | mm;   // wp0 absorbed
    bool zs = m0 | mp;   // ws0 absorbed
    a.wp  = za ? 0.0f : a.wp;   a.wpq = za ? 0.0f : a.wpq;
    a.ws  = zs ? 0.0f : a.ws;   a.wsq = zs ? 0.0f : a.wsq;

    // all loads first (independent, overlap), then adds, then ordered stores
    float2 a0 = shl[a.jc * COLS];
    float2 a1 = shl[(a.jc + 1) * COLS];
    float2 b0 = shl[b.jc * COLS];
    float2 b1 = shl[(b.jc + 1) * COLS];
    a0.x += a.wp; a0.y += a.wpq;
    a1.x += a.ws; a1.y += a.wsq;
    b0.x += b.wp; b0.y += b.wpq;
    b1.x += b.ws; b1.y += b.wsq;
    shl[a.jc * COLS]       = a0;
    shl[(a.jc + 1) * COLS] = a1;
    shl[b.jc * COLS]       = b0;   // after a-stores: overwrites with merged value on collision
    shl[(b.jc + 1) * COLS] = b1;
}

__device__ __forceinline__ void process4(float2* __restrict__ shl,
                                         float4 o, float4 w,
                                         float invd, float nb0)
{
    Contrib c0 = elem_contrib(o.x, w.x, invd, nb0);
    Contrib c1 = elem_contrib(o.y, w.y, invd, nb0);
    Contrib c2 = elem_contrib(o.z, w.z, invd, nb0);
    Contrib c3 = elem_contrib(o.w, w.w, invd, nb0);
    pair_rmw(shl, c0, c1);
    pair_rmw(shl, c2, c3);
}

__global__ __launch_bounds__(32, 8) void fused_k(
    const float4* __restrict__ obs4,
    const float4* __restrict__ wts4,
    const float*  __restrict__ obs_s,
    const float*  __restrict__ wts_s,
    const float*  __restrict__ bins,
    const float*  __restrict__ histo_exp,
    float*        __restrict__ out,
    int nvec, int n)
{
    __shared__ float2 sh[NBINS * COLS];
    const int lane = threadIdx.x;

    #pragma unroll
    for (int i = lane; i < NBINS * COLS; i += 32)
        sh[i] = make_float2(0.0f, 0.0f);
    __syncwarp();

    const float b0   = __ldg(&bins[0]);
    const float bN   = __ldg(&bins[NBINS]);
    const float invd = (float)NBINS / (bN - b0);
    const float nb0  = -b0 * invd;

    float2* shl = &sh[lane];
    const int stride = GRID_BLOCKS * 32;

    // Software-pipelined main loop: two float4-pairs in flight ahead of compute.
    int v0 = blockIdx.x * 32 + lane;
    float4 o0, w0, o1, w1;
    bool h0 = (v0 < nvec);
    bool h1 = (v0 + stride < nvec);
    if (h0) { o0 = obs4[v0];          w0 = wts4[v0]; }
    if (h1) { o1 = obs4[v0 + stride]; w1 = wts4[v0 + stride]; }
    int v = v0 + 2 * stride;
    while (v + stride < nvec) {
        float4 no0 = obs4[v];          float4 nw0 = wts4[v];
        float4 no1 = obs4[v + stride]; float4 nw1 = wts4[v + stride];
        process4(shl, o0, w0, invd, nb0);
        process4(shl, o1, w1, invd, nb0);
        o0 = no0; w0 = nw0; o1 = no1; w1 = nw1;
        v += 2 * stride;
    }
    if (v < nvec) {
        float4 no0 = obs4[v]; float4 nw0 = wts4[v];
        if (h0) process4(shl, o0, w0, invd, nb0);
        if (h1) process4(shl, o1, w1, invd, nb0);
        process4(shl, no0, nw0, invd, nb0);
    } else {
        if (h0) process4(shl, o0, w0, invd, nb0);
        if (h1) process4(shl, o1, w1, invd, nb0);
    }

    // Scalar tail (N % 4), block 0 only (empty for N = 2^25).
    if (blockIdx.x == 0) {
        for (int i = nvec * 4 + lane; i < n; i += 32) {
            Contrib c = elem_contrib(obs_s[i], wts_s[i], invd, nb0);
            float2 x0 = shl[c.jc * COLS];
            x0.x += c.wp; x0.y += c.wpq;
            shl[c.jc * COLS] = x0;
            float2 x1 = shl[(c.jc + 1) * COLS];
            x1.x += c.ws; x1.y += c.wsq;
            shl[(c.jc + 1) * COLS] = x1;
        }
    }
    __syncwarp();

    // Conflict-free rotated per-bin reduction, then one global atomic per bin.
    #pragma unroll
    for (int g = 0; g < 4; g++) {
        int b = g * 32 + lane;
        if (b < NBINS) {
            float h = 0.0f, s = 0.0f;
            #pragma unroll
            for (int t = 0; t < 32; t++) {
                int c = (lane + t) & 31;
                float2 vv = sh[b * COLS + c];
                h += vv.x; s += vv.y;
            }
            atomicAdd(&g_hist[b], h);
            atomicAdd(&g_wss[b], s);
        }
    }

    // Last-block-done: final chi^2 + reset for next graph replay.
    __syncwarp();
    __threadfence();
    unsigned int done = 0;
    if (lane == 0) done = atomicAdd(&g_count, 1u);
    done = __shfl_sync(0xFFFFFFFFu, done, 0);
    if (done == (unsigned)(GRID_BLOCKS - 1)) {
        __threadfence();
        float hs[4], ss[4], he[4];
        float hsum = 0.0f, esum = 0.0f;
        #pragma unroll
        for (int g = 0; g < 4; g++) {
            int b = g * 32 + lane;
            bool ok = (b < NBINS);
            hs[g] = ok ? __ldcg(&g_hist[b]) : 0.0f;
            ss[g] = ok ? __ldcg(&g_wss[b])  : 0.0f;
            he[g] = ok ? __ldg(&histo_exp[b]) : 0.0f;
            hsum += hs[g];
            esum += he[g];
        }
        #pragma unroll
        for (int o = 16; o > 0; o >>= 1) {
            hsum += __shfl_xor_sync(0xFFFFFFFFu, hsum, o);
            esum += __shfl_xor_sync(0xFFFFFFFFu, esum, o);
        }
        const float inv_ss2 = 1.0f / ((hsum + EPSF) * (hsum + EPSF));
        const float inv_se2 = 1.0f / ((esum + EPSF) * (esum + EPSF));
        const float inv_ss  = 1.0f / hsum;
        const float inv_se  = 1.0f / esum;
        float chi = 0.0f;
        #pragma unroll
        for (int g = 0; g < 4; g++) {
            int b = g * 32 + lane;
            if (b < NBINS) {
                float unc_sim = ss[g] * inv_ss2 + EPSF;
                float unc_exp = he[g] * (1.0f - he[g] * inv_se) * inv_se2 + EPSF;
                float d = hs[g] * inv_ss - he[g] * inv_se;
                chi += d * d / (unc_sim + unc_exp);
            }
        }
        #pragma unroll
        for (int o = 16; o > 0; o >>= 1)
            chi += __shfl_xor_sync(0xFFFFFFFFu, chi, o);
        if (lane == 0) out[0] = chi;

        #pragma unroll
        for (int g = 0; g < 4; g++) {
            int b = g * 32 + lane;
            if (b < NBINS) {
                __stcg(&g_hist[b], 0.0f);
                __stcg(&g_wss[b], 0.0f);
            }
        }
        __threadfence();
        if (lane == 0) atomicExch(&g_count, 0u);
    }
}

extern "C" void kernel_launch(void* const* d_in, const int* in_sizes, int n_in,
                              void* d_out, int out_size) {
    const float* sim  = (const float*)d_in[0];
    // d_in[1] = exp_observable: unused in the fixed_binning branch
    const float* wts  = (const float*)d_in[2];
    const float* bins = (const float*)d_in[3];
    const float* he   = (const float*)d_in[4];
    int n    = in_sizes[0];
    int nvec = n / 4;

    cudaFuncSetAttribute(fused_k, cudaFuncAttributePreferredSharedMemoryCarveout, 100);

    fused_k<<<GRID_BLOCKS, 32>>>((const float4*)sim, (const float4*)wts,
                                 sim, wts, bins, he, (float*)d_out, nvec, n);
}

// round 5
// speedup vs baseline: 2.0684x; 1.1867x over previous
#include <cuda_runtime.h>
#include <cuda_bf16.h>

#define NBINS 100
#define EPSF  1e-10f
#define COLS  32
#define GRID_BLOCKS 1216   // 152 SMs * 8 blocks
#define DEPTH 8            // float4-pairs in flight per thread (16 LDG.128)

__device__ float        g_hist[NBINS];
__device__ float        g_wss[NBINS];
__device__ unsigned int g_count;

struct Contrib {
    int   jc;
    float wp, wpq, ws, wsq;
};

__device__ __forceinline__ Contrib elem_contrib(float of, float wf,
                                                float invd, float nb0)
{
    Contrib c;
    float t  = fmaf(of, invd, nb0);          // (of - b0) * invd
    float jf = floorf(t);
    float fr = t - jf;
    int   j  = (int)jf;
    c.jc     = min(max(j, 0), NBINS - 2);
    bool sub  = ((unsigned)j       <= (unsigned)(NBINS - 3)); // -> bin jc+1
    bool plus = ((unsigned)(j - 1) <= (unsigned)(NBINS - 3)); // -> bin jc
    c.ws  = sub  ? fr * wf           : 0.0f;
    c.wp  = plus ? (1.0f - fr) * wf  : 0.0f;
    c.wsq = c.ws * c.ws;
    c.wpq = c.wp * c.wp;
    return c;
}

// Two elements' RMWs with collision merge so all 4 LDS issue before any STS.
__device__ __forceinline__ void pair_rmw(float2* __restrict__ shl,
                                         Contrib a, Contrib b)
{
    int d = b.jc - a.jc;
    bool m0 = (d == 0), mp = (d == 1), mm = (d == -1);
    float addp  = m0 ? a.wp  : (mp ? a.ws  : 0.0f);
    float addpq = m0 ? a.wpq : (mp ? a.wsq : 0.0f);
    float adds  = m0 ? a.ws  : (mm ? a.wp  : 0.0f);
    float addsq = m0 ? a.wsq : (mm ? a.wpq : 0.0f);
    b.wp  += addp;  b.wpq += addpq;
    b.ws  += adds;  b.wsq += addsq;
    bool za = m0 | mm;
    bool zs = m0 | mp;
    a.wp  = za ? 0.0f : a.wp;   a.wpq = za ? 0.0f : a.wpq;
    a.ws  = zs ? 0.0f : a.ws;   a.wsq = zs ? 0.0f : a.wsq;

    float2 a0 = shl[a.jc * COLS];
    float2 a1 = shl[(a.jc + 1) * COLS];
    float2 b0 = shl[b.jc * COLS];
    float2 b1 = shl[(b.jc + 1) * COLS];
    a0.x += a.wp; a0.y += a.wpq;
    a1.x += a.ws; a1.y += a.wsq;
    b0.x += b.wp; b0.y += b.wpq;
    b1.x += b.ws; b1.y += b.wsq;
    shl[a.jc * COLS]       = a0;
    shl[(a.jc + 1) * COLS] = a1;
    shl[b.jc * COLS]       = b0;
    shl[(b.jc + 1) * COLS] = b1;
}

__device__ __forceinline__ void process4(float2* __restrict__ shl,
                                         float4 o, float4 w,
                                         float invd, float nb0)
{
    Contrib c0 = elem_contrib(o.x, w.x, invd, nb0);
    Contrib c1 = elem_contrib(o.y, w.y, invd, nb0);
    Contrib c2 = elem_contrib(o.z, w.z, invd, nb0);
    Contrib c3 = elem_contrib(o.w, w.w, invd, nb0);
    pair_rmw(shl, c0, c1);
    pair_rmw(shl, c2, c3);
}

__global__ __launch_bounds__(32, 8) void fused_k(
    const float4* __restrict__ obs4,
    const float4* __restrict__ wts4,
    const float*  __restrict__ obs_s,
    const float*  __restrict__ wts_s,
    const float*  __restrict__ bins,
    const float*  __restrict__ histo_exp,
    float*        __restrict__ out,
    int nvec, int n)
{
    __shared__ float2 sh[NBINS * COLS];
    const int lane = threadIdx.x;

    #pragma unroll
    for (int i = lane; i < NBINS * COLS; i += 32)
        sh[i] = make_float2(0.0f, 0.0f);
    __syncwarp();

    const float b0   = __ldg(&bins[0]);
    const float bN   = __ldg(&bins[NBINS]);
    const float invd = (float)NBINS / (bN - b0);
    const float nb0  = -b0 * invd;

    float2* shl = &sh[lane];
    const int stride = GRID_BLOCKS * 32;
    const int base   = blockIdx.x * 32 + lane;

    // Deep rotating prefetch pipeline: DEPTH (obs,wts) float4 pairs in flight.
    // OOB slots load a clamped index (L2 hit) with weights zeroed -> contribute
    // nothing, so every slot is processed unconditionally (branch-free).
    float4 O[DEPTH], W[DEPTH];
    #pragma unroll
    for (int d = 0; d < DEPTH; d++) {
        int vi   = base + d * stride;
        bool act = vi < nvec;
        int idx  = act ? vi : (nvec - 1);
        O[d] = obs4[idx];
        float4 ww = wts4[idx];
        if (!act) ww = make_float4(0.0f, 0.0f, 0.0f, 0.0f);
        W[d] = ww;
    }

    for (int v = base; v < nvec; v += DEPTH * stride) {
        #pragma unroll
        for (int d = 0; d < DEPTH; d++) {
            int vi   = v + (DEPTH + d) * stride;
            bool act = vi < nvec;
            int idx  = act ? vi : (nvec - 1);
            float4 no = obs4[idx];
            float4 nw = wts4[idx];
            process4(shl, O[d], W[d], invd, nb0);
            O[d] = no;
            W[d] = act ? nw : make_float4(0.0f, 0.0f, 0.0f, 0.0f);
        }
    }

    // Scalar tail (N % 4), block 0 only (empty for N = 2^25).
    if (blockIdx.x == 0) {
        for (int i = nvec * 4 + lane; i < n; i += 32) {
            Contrib c = elem_contrib(obs_s[i], wts_s[i], invd, nb0);
            float2 x0 = shl[c.jc * COLS];
            x0.x += c.wp; x0.y += c.wpq;
            shl[c.jc * COLS] = x0;
            float2 x1 = shl[(c.jc + 1) * COLS];
            x1.x += c.ws; x1.y += c.wsq;
            shl[(c.jc + 1) * COLS] = x1;
        }
    }
    __syncwarp();

    // Conflict-free rotated per-bin reduction, then one global atomic per bin.
    #pragma unroll
    for (int g = 0; g < 4; g++) {
        int b = g * 32 + lane;
        if (b < NBINS) {
            float h = 0.0f, s = 0.0f;
            #pragma unroll
            for (int t = 0; t < 32; t++) {
                int c = (lane + t) & 31;
                float2 vv = sh[b * COLS + c];
                h += vv.x; s += vv.y;
            }
            atomicAdd(&g_hist[b], h);
            atomicAdd(&g_wss[b], s);
        }
    }

    // Last-block-done: final chi^2 + reset for next graph replay.
    __syncwarp();
    __threadfence();
    unsigned int done = 0;
    if (lane == 0) done = atomicAdd(&g_count, 1u);
    done = __shfl_sync(0xFFFFFFFFu, done, 0);
    if (done == (unsigned)(GRID_BLOCKS - 1)) {
        __threadfence();
        float hs[4], ss[4], he[4];
        float hsum = 0.0f, esum = 0.0f;
        #pragma unroll
        for (int g = 0; g < 4; g++) {
            int b = g * 32 + lane;
            bool ok = (b < NBINS);
            hs[g] = ok ? __ldcg(&g_hist[b]) : 0.0f;
            ss[g] = ok ? __ldcg(&g_wss[b])  : 0.0f;
            he[g] = ok ? __ldg(&histo_exp[b]) : 0.0f;
            hsum += hs[g];
            esum += he[g];
        }
        #pragma unroll
        for (int o = 16; o > 0; o >>= 1) {
            hsum += __shfl_xor_sync(0xFFFFFFFFu, hsum, o);
            esum += __shfl_xor_sync(0xFFFFFFFFu, esum, o);
        }
        const float inv_ss2 = 1.0f / ((hsum + EPSF) * (hsum + EPSF));
        const float inv_se2 = 1.0f / ((esum + EPSF) * (esum + EPSF));
        const float inv_ss  = 1.0f / hsum;
        const float inv_se  = 1.0f / esum;
        float chi = 0.0f;
        #pragma unroll
        for (int g = 0; g < 4; g++) {
            int b = g * 32 + lane;
            if (b < NBINS) {
                float unc_sim = ss[g] * inv_ss2 + EPSF;
                float unc_exp = he[g] * (1.0f - he[g] * inv_se) * inv_se2 + EPSF;
                float d = hs[g] * inv_ss - he[g] * inv_se;
                chi += d * d / (unc_sim + unc_exp);
            }
        }
        #pragma unroll
        for (int o = 16; o > 0; o >>= 1)
            chi += __shfl_xor_sync(0xFFFFFFFFu, chi, o);
        if (lane == 0) out[0] = chi;

        #pragma unroll
        for (int g = 0; g < 4; g++) {
            int b = g * 32 + lane;
            if (b < NBINS) {
                __stcg(&g_hist[b], 0.0f);
                __stcg(&g_wss[b], 0.0f);
            }
        }
        __threadfence();
        if (lane == 0) atomicExch(&g_count, 0u);
    }
}

extern "C" void kernel_launch(void* const* d_in, const int* in_sizes, int n_in,
                              void* d_out, int out_size) {
    const float* sim  = (const float*)d_in[0];
    // d_in[1] = exp_observable: unused in the fixed_binning branch
    const float* wts  = (const float*)d_in[2];
    const float* bins = (const float*)d_in[3];
    const float* he   = (const float*)d_in[4];
    int n    = in_sizes[0];
    int nvec = n / 4;

    cudaFuncSetAttribute(fused_k, cudaFuncAttributePreferredSharedMemoryCarveout, 100);

    fused_k<<<GRID_BLOCKS, 32>>>((const float4*)sim, (const float4*)wts,
                                 sim, wts, bins, he, (float*)d_out, nvec, n);
}